// round 3
// baseline (speedup 1.0000x reference)
#include <cuda_runtime.h>

#define NB   512   // threads per block; 2 threads per row
#define ROWS 256   // rows per block
#define NBLK 256   // 256*256 = 65536 rows
#define ALPHA 0.01f

// ---- shared memory layout (float offsets, all 16B-aligned) ----
#define S_WIN   0        // 3 * 8*64 = 1536
#define S_BIN   1536     // 3 * 64   = 192
#define S_WA1   1728     // 64
#define S_WA2   1792     // 64
#define S_WO1   1856     // 10*32 = 320
#define S_BO1   2176     // 32
#define S_WO2   2208     // 32*16 = 512
#define S_BO2   2720     // 16
#define S_WO3   2736     // 16
#define S_BO3   2752     // 1 (+3 pad)
#define S_WFC1  2756     // 90*64 = 5760
#define S_BFC1  8516     // 64
#define S_WIH   8580     // 192*64 = 12288
#define S_BIH   20868    // 192
#define S_WHH   21060    // 192*64 = 12288
#define S_BHH   33348    // 192
#define S_WFC2  33540    // 64*5 = 320
#define S_BFC2  33860    // 5 (+3 pad)
#define S_OBS   33868    // 256*85 = 21760; later reused as x-scratch (stride 68)
#define S_TOT   (33868 + 21760)   // 55628 floats = 222512 bytes

#define XSTRIDE 68   // x scratch stride: (68*r+4k) mod 32 distinct within 8-lane phase

__device__ __forceinline__ float lrelu(float v) { return fmaxf(v, ALPHA * v); }
__device__ __forceinline__ float fsig(float v)  { return __fdividef(1.0f, 1.0f + __expf(-v)); }
__device__ __forceinline__ float ftanh(float v) { return 1.0f - __fdividef(2.0f, __expf(2.0f * v) + 1.0f); }

__global__ void __launch_bounds__(NB, 1)
atom_rnn_kernel(const float* __restrict__ g_obs, const float* __restrict__ g_hid,
                const float* __restrict__ w_in0, const float* __restrict__ b_in0,
                const float* __restrict__ w_in1, const float* __restrict__ b_in1,
                const float* __restrict__ w_in2, const float* __restrict__ b_in2,
                const float* __restrict__ g_W,  const float* __restrict__ g_a,
                const float* __restrict__ w_o1, const float* __restrict__ b_o1,
                const float* __restrict__ w_o2, const float* __restrict__ b_o2,
                const float* __restrict__ w_o3, const float* __restrict__ b_o3,
                const float* __restrict__ w_fc1, const float* __restrict__ b_fc1,
                const float* __restrict__ w_ih, const float* __restrict__ w_hh,
                const float* __restrict__ b_ih, const float* __restrict__ b_hh,
                const float* __restrict__ w_fc2, const float* __restrict__ b_fc2,
                float* out_q, float* out_h)
{
    extern __shared__ float sm[];
    const int tid  = threadIdx.x;
    const int lrow = tid & 255;       // row within block
    const int half = tid >> 8;        // 0 or 1 (warp-uniform: warps 0-7 / 8-15)
    const int row  = blockIdx.x * ROWS + lrow;

    // ---------------- stage weights into shared (vectorized, 512 threads) ----------------
    #define CPY4(off, src, n) { const float4* s4_ = (const float4*)(src); \
                                float4* d4_ = (float4*)&sm[off]; \
                                for (int i = tid; i < (n)/4; i += NB) d4_[i] = s4_[i]; }
    CPY4(S_WIN,        w_in0, 512);
    CPY4(S_WIN + 512,  w_in1, 512);
    CPY4(S_WIN + 1024, w_in2, 512);
    CPY4(S_BIN,        b_in0, 64);
    CPY4(S_BIN + 64,   b_in1, 64);
    CPY4(S_BIN + 128,  b_in2, 64);
    CPY4(S_WO1, w_o1, 320);  CPY4(S_BO1, b_o1, 32);
    CPY4(S_WO2, w_o2, 512);  CPY4(S_BO2, b_o2, 16);
    CPY4(S_WO3, w_o3, 16);
    CPY4(S_WFC1, w_fc1, 5760); CPY4(S_BFC1, b_fc1, 64);
    CPY4(S_WIH, w_ih, 12288);  CPY4(S_BIH, b_ih, 192);
    CPY4(S_WHH, w_hh, 12288);  CPY4(S_BHH, b_hh, 192);
    CPY4(S_WFC2, w_fc2, 320);
    #undef CPY4
    if (tid == 0) sm[S_BO3] = b_o3[0];
    if (tid >= 32 && tid < 37) sm[S_BFC2 + tid - 32] = b_fc2[tid - 32];

    // Wa1 = W @ a[:64], Wa2 = W @ a[64:]
    if (tid < 128) {
        const int j = tid & 63;
        const float* av = g_a + ((tid < 64) ? 0 : 64);
        const float* wr = g_W + j * 64;
        float s = 0.f;
        #pragma unroll 8
        for (int m = 0; m < 64; ++m) s = fmaf(wr[m], av[m], s);
        sm[((tid < 64) ? S_WA1 : S_WA2) + j] = s;
    }

    // stage obs tile (coalesced, vectorized)
    {
        const float4* src4 = (const float4*)(g_obs + (size_t)blockIdx.x * ROWS * 85);
        float4* dst4 = (float4*)&sm[S_OBS];
        for (int i = tid; i < ROWS * 85 / 4; i += NB) dst4[i] = src4[i];
    }
    __syncthreads();

    const float* orow = &sm[S_OBS + lrow * 85];   // stride 85: conflict-free scalar LDS
    float* whout = out_h + (size_t)row * 64;      // temp scratch for wh exchange
    float* qrow  = out_q + (size_t)row * 5;       // temp scratch for hpv / q partials

    // ---------------- stage 1: 5 tokens per half -> (wh1,wh2) pairs ----------------
    #pragma unroll
    for (int tt = 0; tt < 5; ++tt) {
        const int sel = half ? ((tt < 4) ? 1 : 2) : 0;
        float o[8];
        #pragma unroll
        for (int f = 0; f < 8; ++f) {
            int idx = half * 40 + tt * 8 + 4 + f;        // (t*8+f+4) % 80
            if (idx >= 80) idx -= 80;
            o[f] = orow[idx];
        }
        const float4* w4   = (const float4*)&sm[S_WIN + sel * 512];
        const float4* b4   = (const float4*)&sm[S_BIN + sel * 64];
        const float4* wa14 = (const float4*)&sm[S_WA1];
        const float4* wa24 = (const float4*)&sm[S_WA2];
        float s1 = 0.f, s2 = 0.f;
        #pragma unroll 4
        for (int jv = 0; jv < 16; ++jv) {
            float4 acc = b4[jv];
            #pragma unroll
            for (int f = 0; f < 8; ++f) {
                float4 wv = w4[f * 16 + jv];
                acc.x = fmaf(o[f], wv.x, acc.x);
                acc.y = fmaf(o[f], wv.y, acc.y);
                acc.z = fmaf(o[f], wv.z, acc.z);
                acc.w = fmaf(o[f], wv.w, acc.w);
            }
            acc.x = lrelu(acc.x); acc.y = lrelu(acc.y);
            acc.z = lrelu(acc.z); acc.w = lrelu(acc.w);
            float4 a1 = wa14[jv], a2 = wa24[jv];
            s1 = fmaf(acc.x, a1.x, s1); s1 = fmaf(acc.y, a1.y, s1);
            s1 = fmaf(acc.z, a1.z, s1); s1 = fmaf(acc.w, a1.w, s1);
            s2 = fmaf(acc.x, a2.x, s2); s2 = fmaf(acc.y, a2.y, s2);
            s2 = fmaf(acc.z, a2.z, s2); s2 = fmaf(acc.w, a2.w, s2);
        }
        const int t = half * 5 + tt;
        *(float2*)&whout[2 * t] = make_float2(s1, s2);   // exchange via global scratch
    }
    __syncthreads();   // wh visible block-wide

    float wh1[10], wh2[10];
    #pragma unroll
    for (int t = 0; t < 10; ++t) {
        float2 v = *(const float2*)&whout[2 * t];
        wh1[t] = v.x; wh2[t] = v.y;
    }

    // ---------------- stage 2: attention rows (3 for half0, 2 for half1) ----------------
    float mx1[5], dinv1[5];
    #pragma unroll
    for (int c = 0; c < 5; ++c) {
        float mx = -1e30f;
        #pragma unroll
        for (int r2 = 0; r2 < 5; ++r2) mx = fmaxf(mx, lrelu(wh1[5 + c] + wh2[r2]));
        float d = 0.f;
        #pragma unroll
        for (int r2 = 0; r2 < 5; ++r2) d += __expf(lrelu(wh1[5 + c] + wh2[r2]) - mx);
        mx1[c] = mx; dinv1[c] = __fdividef(1.0f, d);
    }

    #pragma unroll
    for (int rr = 0; rr < 3; ++rr) {
        if (half && rr == 2) break;
        const int r = half ? (3 + rr) : rr;
        const float w1r = half ? wh1[3 + rr] : wh1[rr];
        const float w2r = half ? wh2[3 + rr] : wh2[rr];
        float att[10];
        {
            float ev[5]; float mx = -1e30f;
            #pragma unroll
            for (int c = 0; c < 5; ++c) {
                float v = lrelu(w1r + wh2[5 + c]);
                ev[c] = v; mx = fmaxf(mx, v);
            }
            float d = 0.f;
            #pragma unroll
            for (int c = 0; c < 5; ++c) { float e_ = __expf(ev[c] - mx); att[c] = e_; d += e_; }
            float inv = __fdividef(1.0f, d);
            #pragma unroll
            for (int c = 0; c < 5; ++c) att[c] *= inv;
            #pragma unroll
            for (int c = 0; c < 5; ++c)
                att[5 + c] = __expf(lrelu(wh1[5 + c] + w2r) - mx1[c]) * dinv1[c];
        }
        float h1[32];
        {
            const float4* wv4 = (const float4*)&sm[S_WO1];
            const float4* bv4 = (const float4*)&sm[S_BO1];
            #pragma unroll
            for (int jv = 0; jv < 8; ++jv) {
                float4 acc = bv4[jv];
                #pragma unroll
                for (int k = 0; k < 10; ++k) {
                    float4 wv = wv4[k * 8 + jv];
                    acc.x = fmaf(att[k], wv.x, acc.x);
                    acc.y = fmaf(att[k], wv.y, acc.y);
                    acc.z = fmaf(att[k], wv.z, acc.z);
                    acc.w = fmaf(att[k], wv.w, acc.w);
                }
                h1[4*jv]   = lrelu(acc.x); h1[4*jv+1] = lrelu(acc.y);
                h1[4*jv+2] = lrelu(acc.z); h1[4*jv+3] = lrelu(acc.w);
            }
        }
        float h2v[16];
        {
            const float4* wv4 = (const float4*)&sm[S_WO2];
            const float4* bv4 = (const float4*)&sm[S_BO2];
            #pragma unroll
            for (int jv = 0; jv < 4; ++jv) {
                float4 acc = bv4[jv];
                #pragma unroll
                for (int k = 0; k < 32; ++k) {
                    float4 wv = wv4[k * 4 + jv];
                    acc.x = fmaf(h1[k], wv.x, acc.x);
                    acc.y = fmaf(h1[k], wv.y, acc.y);
                    acc.z = fmaf(h1[k], wv.z, acc.z);
                    acc.w = fmaf(h1[k], wv.w, acc.w);
                }
                h2v[4*jv]   = lrelu(acc.x); h2v[4*jv+1] = lrelu(acc.y);
                h2v[4*jv+2] = lrelu(acc.z); h2v[4*jv+3] = lrelu(acc.w);
            }
        }
        float v = sm[S_BO3];
        {
            const float4* wv4 = (const float4*)&sm[S_WO3];
            #pragma unroll
            for (int kv = 0; kv < 4; ++kv) {
                float4 wv = wv4[kv];
                v = fmaf(h2v[4*kv],   wv.x, v);
                v = fmaf(h2v[4*kv+1], wv.y, v);
                v = fmaf(h2v[4*kv+2], wv.z, v);
                v = fmaf(h2v[4*kv+3], wv.w, v);
            }
        }
        qrow[r] = lrelu(v);                           // hpv exchange via global scratch
    }
    __syncthreads();

    // softmax over hpv -> obs_out
    float obs_out[5];
    {
        float hp[5];
        #pragma unroll
        for (int r = 0; r < 5; ++r) hp[r] = qrow[r];
        float mx = fmaxf(fmaxf(fmaxf(hp[0], hp[1]), fmaxf(hp[2], hp[3])), hp[4]);
        float d = 0.f;
        #pragma unroll
        for (int r = 0; r < 5; ++r) { obs_out[r] = __expf(hp[r] - mx); d += obs_out[r]; }
        float inv = __fdividef(1.0f, d);
        #pragma unroll
        for (int r = 0; r < 5; ++r) obs_out[r] *= inv;
    }

    // load hi early (latency overlaps fc1)
    const float* hid_row = g_hid + (size_t)row * 64;
    float hi[64];
    {
        const float4* hp4 = (const float4*)hid_row;
        #pragma unroll
        for (int i = 0; i < 16; ++i) {
            float4 v = hp4[i];
            hi[4*i] = v.x; hi[4*i+1] = v.y; hi[4*i+2] = v.z; hi[4*i+3] = v.w;
        }
    }

    // ---------------- stage 3: fc1, half computes 32 outputs ----------------
    const int jbase = half * 32;
    float xacc[32];
    {
        const float4* bv4 = (const float4*)&sm[S_BFC1 + jbase];
        #pragma unroll
        for (int jv = 0; jv < 8; ++jv) {
            float4 b = bv4[jv];
            xacc[4*jv] = b.x; xacc[4*jv+1] = b.y; xacc[4*jv+2] = b.z; xacc[4*jv+3] = b.w;
        }
    }
    #pragma unroll 2
    for (int k = 0; k < 85; ++k) {
        const float ok = orow[k];
        const float4* wr4 = (const float4*)&sm[S_WFC1 + k * 64 + jbase];
        #pragma unroll
        for (int jv = 0; jv < 8; ++jv) {
            float4 wv = wr4[jv];
            xacc[4*jv]   = fmaf(ok, wv.x, xacc[4*jv]);
            xacc[4*jv+1] = fmaf(ok, wv.y, xacc[4*jv+1]);
            xacc[4*jv+2] = fmaf(ok, wv.z, xacc[4*jv+2]);
            xacc[4*jv+3] = fmaf(ok, wv.w, xacc[4*jv+3]);
        }
    }
    #pragma unroll
    for (int m = 0; m < 5; ++m) {
        const float om = obs_out[m];
        const float4* wr4 = (const float4*)&sm[S_WFC1 + (85 + m) * 64 + jbase];
        #pragma unroll
        for (int jv = 0; jv < 8; ++jv) {
            float4 wv = wr4[jv];
            xacc[4*jv]   = fmaf(om, wv.x, xacc[4*jv]);
            xacc[4*jv+1] = fmaf(om, wv.y, xacc[4*jv+1]);
            xacc[4*jv+2] = fmaf(om, wv.z, xacc[4*jv+2]);
            xacc[4*jv+3] = fmaf(om, wv.w, xacc[4*jv+3]);
        }
    }
    #pragma unroll
    for (int j = 0; j < 32; ++j) xacc[j] = fmaxf(xacc[j], 0.f);

    __syncthreads();   // all obs reads done -> safe to overwrite region with x
    {
        float4* xw4 = (float4*)&sm[S_OBS + lrow * XSTRIDE + jbase];
        #pragma unroll
        for (int jv = 0; jv < 8; ++jv)
            xw4[jv] = make_float4(xacc[4*jv], xacc[4*jv+1], xacc[4*jv+2], xacc[4*jv+3]);
    }
    __syncthreads();   // full x[64] visible per row

    // ---------------- stage 4: GRU, half computes j in [jbase, jbase+32) ----------------
    const float4* xr4 = (const float4*)&sm[S_OBS + lrow * XSTRIDE];
    float hq0 = 0.f, hq1 = 0.f, hq2 = 0.f, hq3 = 0.f, hq4 = 0.f;
    if (!half) {
        hq0 = sm[S_BFC2];     hq1 = sm[S_BFC2 + 1]; hq2 = sm[S_BFC2 + 2];
        hq3 = sm[S_BFC2 + 3]; hq4 = sm[S_BFC2 + 4];
    }

    #pragma unroll 1
    for (int jj = 0; jj < 32; ++jj) {
        const int j = jbase + jj;
        const float4* wiR = (const float4*)&sm[S_WIH + j * 64];
        const float4* wiZ = (const float4*)&sm[S_WIH + (64 + j) * 64];
        const float4* wiN = (const float4*)&sm[S_WIH + (128 + j) * 64];
        const float4* whR = (const float4*)&sm[S_WHH + j * 64];
        const float4* whZ = (const float4*)&sm[S_WHH + (64 + j) * 64];
        const float4* whN = (const float4*)&sm[S_WHH + (128 + j) * 64];
        float axr = sm[S_BIH + j],       ahr = sm[S_BHH + j];
        float axz = sm[S_BIH + 64 + j],  ahz = sm[S_BHH + 64 + j];
        float axn = sm[S_BIH + 128 + j], ahn = sm[S_BHH + 128 + j];
        #pragma unroll
        for (int kv = 0; kv < 16; ++kv) {
            float4 xv = xr4[kv];
            float4 wr = wiR[kv], wz = wiZ[kv], wn = wiN[kv];
            float4 vr = whR[kv], vz = whZ[kv], vn = whN[kv];
            axr = fmaf(xv.x, wr.x, axr); axr = fmaf(xv.y, wr.y, axr);
            axr = fmaf(xv.z, wr.z, axr); axr = fmaf(xv.w, wr.w, axr);
            ahr = fmaf(hi[4*kv],   vr.x, ahr); ahr = fmaf(hi[4*kv+1], vr.y, ahr);
            ahr = fmaf(hi[4*kv+2], vr.z, ahr); ahr = fmaf(hi[4*kv+3], vr.w, ahr);
            axz = fmaf(xv.x, wz.x, axz); axz = fmaf(xv.y, wz.y, axz);
            axz = fmaf(xv.z, wz.z, axz); axz = fmaf(xv.w, wz.w, axz);
            ahz = fmaf(hi[4*kv],   vz.x, ahz); ahz = fmaf(hi[4*kv+1], vz.y, ahz);
            ahz = fmaf(hi[4*kv+2], vz.z, ahz); ahz = fmaf(hi[4*kv+3], vz.w, ahz);
            axn = fmaf(xv.x, wn.x, axn); axn = fmaf(xv.y, wn.y, axn);
            axn = fmaf(xv.z, wn.z, axn); axn = fmaf(xv.w, wn.w, axn);
            ahn = fmaf(hi[4*kv],   vn.x, ahn); ahn = fmaf(hi[4*kv+1], vn.y, ahn);
            ahn = fmaf(hi[4*kv+2], vn.z, ahn); ahn = fmaf(hi[4*kv+3], vn.w, ahn);
        }
        const float r_ = fsig(axr + ahr);
        const float z_ = fsig(axz + ahz);
        const float n_ = ftanh(fmaf(r_, ahn, axn));
        const float hj = __ldg(hid_row + j);          // h_in[j]; L1/L2 hit (row already loaded)
        const float h_ = n_ + z_ * (hj - n_);
        whout[j] = h_;                                // final h output (overwrites wh scratch)
        hq0 = fmaf(h_, sm[S_WFC2 + j * 5],     hq0);
        hq1 = fmaf(h_, sm[S_WFC2 + j * 5 + 1], hq1);
        hq2 = fmaf(h_, sm[S_WFC2 + j * 5 + 2], hq2);
        hq3 = fmaf(h_, sm[S_WFC2 + j * 5 + 3], hq3);
        hq4 = fmaf(h_, sm[S_WFC2 + j * 5 + 4], hq4);
    }

    // ---------------- q: combine half partials via global scratch ----------------
    if (half) {
        qrow[0] = hq0; qrow[1] = hq1; qrow[2] = hq2; qrow[3] = hq3; qrow[4] = hq4;
    }
    __syncthreads();
    if (!half) {
        qrow[0] += hq0; qrow[1] += hq1; qrow[2] += hq2; qrow[3] += hq3; qrow[4] += hq4;
    }
}

extern "C" void kernel_launch(void* const* d_in, const int* in_sizes, int n_in,
                              void* d_out, int out_size)
{
    const float* g_obs  = (const float*)d_in[0];
    const float* g_hid  = (const float*)d_in[1];
    const float* w_in0  = (const float*)d_in[2];
    const float* b_in0  = (const float*)d_in[3];
    const float* w_in1  = (const float*)d_in[4];
    const float* b_in1  = (const float*)d_in[5];
    const float* w_in2  = (const float*)d_in[6];
    const float* b_in2  = (const float*)d_in[7];
    const float* g_W    = (const float*)d_in[8];
    const float* g_a    = (const float*)d_in[9];
    const float* w_o1   = (const float*)d_in[10];
    const float* b_o1   = (const float*)d_in[11];
    const float* w_o2   = (const float*)d_in[12];
    const float* b_o2   = (const float*)d_in[13];
    const float* w_o3   = (const float*)d_in[14];
    const float* b_o3   = (const float*)d_in[15];
    const float* w_fc1  = (const float*)d_in[16];
    const float* b_fc1  = (const float*)d_in[17];
    const float* w_ih   = (const float*)d_in[18];
    const float* w_hh   = (const float*)d_in[19];
    const float* b_ih   = (const float*)d_in[20];
    const float* b_hh   = (const float*)d_in[21];
    const float* w_fc2  = (const float*)d_in[22];
    const float* b_fc2  = (const float*)d_in[23];

    float* out   = (float*)d_out;
    float* out_q = out;                          // q: (65536, 5)
    float* out_h = out + (size_t)65536 * 5;      // h: (65536, 64)

    const int smem_bytes = S_TOT * 4;            // 222512 B
    cudaFuncSetAttribute(atom_rnn_kernel,
                         cudaFuncAttributeMaxDynamicSharedMemorySize, smem_bytes);

    atom_rnn_kernel<<<NBLK, NB, smem_bytes>>>(
        g_obs, g_hid, w_in0, b_in0, w_in1, b_in1, w_in2, b_in2, g_W, g_a,
        w_o1, b_o1, w_o2, b_o2, w_o3, b_o3, w_fc1, b_fc1,
        w_ih, w_hh, b_ih, b_hh, w_fc2, b_fc2, out_q, out_h);
}